// round 4
// baseline (speedup 1.0000x reference)
#include <cuda_runtime.h>
#include <math.h>
#include <float.h>

// ---------------- problem constants ----------------
#define NB   2
#define NN   1024
#define NKE  32
#define DIM  512
#define MSG  256
#define NH   16
#define HD   64
#define ROWS_MSG  (NB*NN*NKE)   // 65536
#define ROWS_NODE (NB*NN)       // 2048

// ---------------- scratch (static device globals; no runtime alloc) ----------------
// Reused buffers (lifetimes verified):
//   g_bufA: msg0 (until LN read) -> msg (final messages)
//   g_bufB: ln   (until h1 read) -> t (leaky(msg@W_msg))
__device__ float g_bufA[ROWS_MSG*MSG];
__device__ float g_bufB[ROWS_MSG*MSG];
__device__ float g_h1  [ROWS_MSG*4*MSG];
__device__ float g_node_msg[ROWS_NODE*MSG];
__device__ float g_node_tgt[ROWS_NODE*MSG];
__device__ float g_ab  [ROWS_MSG*NH];
__device__ float g_attn[ROWS_MSG*NH];
__device__ float g_P   [ROWS_NODE*NH*MSG];
__device__ float g_og  [ROWS_NODE*NH*HD];
__device__ float g_gate[ROWS_NODE*MSG];
__device__ float g_gatg[ROWS_NODE*NH*HD];
__device__ float g_o   [ROWS_NODE*MSG];
__device__ float g_dh  [ROWS_NODE*DIM];
__device__ float g_node2[ROWS_NODE*DIM];
__device__ float g_nln [ROWS_NODE*DIM];
__device__ float g_h2  [ROWS_NODE*4*DIM];

// ---------------- generic tiled GEMM with fused epilogues ----------------
#define BM 64
#define BN 64
#define BK 16
#define PAD 4   // 16B-aligned fragments -> float4 shared loads

__device__ __forceinline__ float gelu_exact(float x) {
    return 0.5f * x * (1.0f + erff(x * 0.70710678118654752f));
}
__device__ __forceinline__ float sigmoidf_(float x) {
    return 1.0f / (1.0f + expf(-x));
}

// MODE: 0 plain | 1 +bias | 2 gelu(+bias) | 3 leaky | 4 (+bias)*rowmask
//       5 msg0 (acc + gather(node_msg)*mask_bw + node_tgt)
//       6 aux1 + aux2 + acc | 7 aux1 + acc + bias | 8 sigmoid(aux1)*acc
template<int MODE>
__global__ __launch_bounds__(256) void gemm_kernel(
    const float* __restrict__ A, int lda,
    const float* __restrict__ B, int ldb,
    float* __restrict__ C, int ldc,
    int M, int N, int K,
    const float* __restrict__ bias,
    const float* __restrict__ aux1,
    const float* __restrict__ aux2,
    const int*   __restrict__ idx,
    const float* __restrict__ auxf,
    const int*   __restrict__ rowmask)
{
    __shared__ float As[BK][BM+PAD];
    __shared__ float Bs[BK][BN+PAD];
    const int tid = threadIdx.x;
    const int row0 = blockIdx.y * BM, col0 = blockIdx.x * BN;
    const int ty = tid >> 4, tx = tid & 15;

    float acc[4][4] = {};

    // A-tile loader: thread -> (row mm, 4 consecutive k) ; 256 threads cover 64x16
    const int a_mm = tid >> 2;            // 0..63
    const int a_k4 = (tid & 3) * 4;       // 0,4,8,12
    // B-tile loader: thread -> (k row kk, 4 consecutive n) ; 256 threads cover 16x64
    const int b_kk = tid >> 4;            // 0..15
    const int b_n4 = (tid & 15) * 4;      // 0..60

    for (int kt = 0; kt < K; kt += BK) {
        {
            int gr = row0 + a_mm;
            float4 v;
            if (gr < M) {
                v = *reinterpret_cast<const float4*>(&A[(size_t)gr * lda + kt + a_k4]);
            } else {
                v = make_float4(0.f, 0.f, 0.f, 0.f);
            }
            As[a_k4 + 0][a_mm] = v.x;
            As[a_k4 + 1][a_mm] = v.y;
            As[a_k4 + 2][a_mm] = v.z;
            As[a_k4 + 3][a_mm] = v.w;
        }
        {
            int gc = col0 + b_n4;
            const float* brow = &B[(size_t)(kt + b_kk) * ldb];
            if (gc + 3 < N) {
                float4 v = *reinterpret_cast<const float4*>(&brow[gc]);
                *reinterpret_cast<float4*>(&Bs[b_kk][b_n4]) = v;
            } else {
                #pragma unroll
                for (int j = 0; j < 4; j++)
                    Bs[b_kk][b_n4 + j] = (gc + j < N) ? brow[gc + j] : 0.f;
            }
        }
        __syncthreads();
        #pragma unroll
        for (int kk = 0; kk < BK; kk++) {
            float4 av = *reinterpret_cast<const float4*>(&As[kk][ty * 4]);
            float4 bv = *reinterpret_cast<const float4*>(&Bs[kk][tx * 4]);
            float a[4] = {av.x, av.y, av.z, av.w};
            float b[4] = {bv.x, bv.y, bv.z, bv.w};
            #pragma unroll
            for (int i = 0; i < 4; i++)
                #pragma unroll
                for (int j = 0; j < 4; j++)
                    acc[i][j] = fmaf(a[i], b[j], acc[i][j]);
        }
        __syncthreads();
    }

    #pragma unroll
    for (int i = 0; i < 4; i++) {
        int r = row0 + ty*4 + i;
        if (r >= M) continue;
        #pragma unroll
        for (int j = 0; j < 4; j++) {
            int c = col0 + tx*4 + j;
            if (c >= N) continue;
            float v = acc[i][j];
            if (MODE == 1) {
                v += bias[c];
            } else if (MODE == 2) {
                v = gelu_exact(v + bias[c]);
            } else if (MODE == 3) {
                v = (v > 0.f) ? v : 0.01f * v;
            } else if (MODE == 4) {
                v += bias[c];
                if (rowmask[r] == 0) v = 0.f;
            } else if (MODE == 5) {
                int bidx = r >> 15;            // 32768 msg rows per batch
                int node = r >> 5;             // b*NN + n
                v += aux1[(size_t)(bidx*NN + idx[r]) * MSG + c] * auxf[r]
                   + aux2[(size_t)node * MSG + c];
            } else if (MODE == 6) {
                v = aux1[(size_t)r*ldc + c] + aux2[(size_t)r*ldc + c] + v;
            } else if (MODE == 7) {
                v = aux1[(size_t)r*ldc + c] + v + bias[c];
            } else if (MODE == 8) {
                v *= sigmoidf_(aux1[(size_t)r*ldc + c]);
            }
            C[(size_t)r * ldc + c] = v;
        }
    }
}

// ---------------- LayerNorm (one block per row) ----------------
__global__ __launch_bounds__(256) void ln_kernel(
    const float* __restrict__ x, float* __restrict__ y,
    const float* __restrict__ g, const float* __restrict__ b, int width)
{
    int row = blockIdx.x;
    const float* xr = x + (size_t)row * width;
    float s = 0.f, sq = 0.f;
    for (int c = threadIdx.x; c < width; c += blockDim.x) {
        float v = xr[c]; s += v; sq += v * v;
    }
    __shared__ float sh[64];
    #pragma unroll
    for (int o = 16; o > 0; o >>= 1) {
        s  += __shfl_xor_sync(0xFFFFFFFFu, s,  o);
        sq += __shfl_xor_sync(0xFFFFFFFFu, sq, o);
    }
    int w = threadIdx.x >> 5, l = threadIdx.x & 31;
    if (l == 0) { sh[w] = s; sh[32 + w] = sq; }
    __syncthreads();
    if (threadIdx.x == 0) {
        float ts = 0.f, tq = 0.f;
        int nw = blockDim.x >> 5;
        for (int i = 0; i < nw; i++) { ts += sh[i]; tq += sh[32 + i]; }
        sh[0] = ts; sh[32] = tq;
    }
    __syncthreads();
    float mean = sh[0] / width;
    float var  = sh[32] / width - mean * mean;
    float rstd = rsqrtf(var + 1e-5f);
    float* yr = y + (size_t)row * width;
    for (int c = threadIdx.x; c < width; c += blockDim.x)
        yr[c] = (xr[c] - mean) * rstd * g[c] + b[c];
}

// ---------------- masked softmax over k, per (node, head) ----------------
__global__ __launch_bounds__(512) void softmax_kernel(
    const float* __restrict__ ab, const int* __restrict__ em,
    float* __restrict__ attn)
{
    int node = blockIdx.x;
    int h = threadIdx.x >> 5, k = threadIdx.x & 31;
    int ridx = node * NKE + k;
    float v = em[ridx] ? ab[(size_t)ridx * NH + h] : -FLT_MAX;
    float m = v;
    #pragma unroll
    for (int o = 16; o > 0; o >>= 1) m = fmaxf(m, __shfl_xor_sync(0xFFFFFFFFu, m, o));
    float e = expf(v - m);
    float s = e;
    #pragma unroll
    for (int o = 16; o > 0; o >>= 1) s += __shfl_xor_sync(0xFFFFFFFFu, s, o);
    attn[(size_t)ridx * NH + h] = e / s;
}

// ---------------- P[node,h,c] = sum_k attn[k,h] * msg[k,c] ----------------
__global__ __launch_bounds__(256) void pmat_kernel(
    const float* __restrict__ msg, const float* __restrict__ attn,
    float* __restrict__ P)
{
    __shared__ float ms[NKE][MSG];   // 32 KB
    __shared__ float as[NKE][NH];    // 2 KB
    int node = blockIdx.x;
    for (int e = threadIdx.x; e < NKE * MSG; e += 256)
        ms[e >> 8][e & 255] = msg[(size_t)node * NKE * MSG + e];
    for (int e = threadIdx.x; e < NKE * NH; e += 256)
        as[e >> 4][e & 15] = attn[(size_t)node * NKE * NH + e];
    __syncthreads();
    int c = threadIdx.x;   // 0..255
    #pragma unroll 1
    for (int h = 0; h < NH; h++) {
        float acc = 0.f;
        #pragma unroll
        for (int k = 0; k < NKE; k++) acc = fmaf(as[k][h], ms[k][c], acc);
        P[(size_t)node * NH * MSG + h * MSG + c] = acc;
    }
}

// ---------------- gated mean-pool over k ----------------
__global__ __launch_bounds__(256) void pool_kernel(
    const float* __restrict__ msg, const int* __restrict__ em,
    const float* __restrict__ gate_lin, float* __restrict__ o)
{
    int node = blockIdx.x;
    __shared__ float emf[NKE];
    __shared__ float cnt_s;
    if (threadIdx.x < NKE) emf[threadIdx.x] = (float)em[node * NKE + threadIdx.x];
    __syncthreads();
    if (threadIdx.x == 0) {
        float c = 0.f;
        for (int k = 0; k < NKE; k++) c += emf[k];
        cnt_s = c;
    }
    __syncthreads();
    float inv = 1.f / (cnt_s + 1e-6f);
    int c = threadIdx.x;   // 0..255
    float acc = 0.f;
    #pragma unroll
    for (int k = 0; k < NKE; k++)
        acc = fmaf(emf[k], msg[((size_t)node * NKE + k) * MSG + c], acc);
    float gl = gate_lin[(size_t)node * MSG + c];
    o[(size_t)node * MSG + c] = acc * inv * sigmoidf_(gl);
}

// ---------------- host side ----------------
struct EP {
    const float* bias = nullptr;
    const float* a1 = nullptr;
    const float* a2 = nullptr;
    const int*   idx = nullptr;
    const float* af = nullptr;
    const int*   rm = nullptr;
};

template<int MODE>
static void gemm(const float* A, int lda, const float* B, int ldb,
                 float* C, int ldc, int M, int N, int K, EP e = EP())
{
    dim3 g((N + BN - 1) / BN, (M + BM - 1) / BM);
    gemm_kernel<MODE><<<g, 256>>>(A, lda, B, ldb, C, ldc, M, N, K,
                                  e.bias, e.a1, e.a2, e.idx, e.af, e.rm);
}

extern "C" void kernel_launch(void* const* d_in, const int* in_sizes, int n_in,
                              void* d_out, int out_size)
{
    const float* node_repr  = (const float*)d_in[0];
    const float* edge_repr  = (const float*)d_in[1];
    const int*   edge_index = (const int*)  d_in[2];
    const int*   edge_mask  = (const int*)  d_in[3];
    const float* mask_bw    = (const float*)d_in[4];
    const float* W_edge_msg = (const float*)d_in[5];
    const float* W_node_src = (const float*)d_in[6];
    const float* W_node_tgt = (const float*)d_in[7];
    const float* msg_ln_g   = (const float*)d_in[8];
    const float* msg_ln_b   = (const float*)d_in[9];
    const float* msg_W1     = (const float*)d_in[10];
    const float* msg_b1     = (const float*)d_in[11];
    const float* msg_W2     = (const float*)d_in[12];
    const float* msg_b2     = (const float*)d_in[13];
    const float* W_gate     = (const float*)d_in[14];
    const float* b_gate     = (const float*)d_in[15];
    const float* W_out      = (const float*)d_in[16];
    const float* W_msg      = (const float*)d_in[17];
    const float* W_attn_bias= (const float*)d_in[18];
    const float* W_gat_value= (const float*)d_in[19];
    const float* W_gat_gate = (const float*)d_in[20];
    const float* b_gat_gate = (const float*)d_in[21];
    const float* W_gat_out  = (const float*)d_in[22];
    const float* node_ln_g  = (const float*)d_in[23];
    const float* node_ln_b  = (const float*)d_in[24];
    const float* node_W1    = (const float*)d_in[25];
    const float* node_b1    = (const float*)d_in[26];
    const float* node_W2    = (const float*)d_in[27];
    const float* node_b2    = (const float*)d_in[28];

    float *p_bufA, *p_bufB, *p_h1, *p_node_msg, *p_node_tgt,
          *p_ab, *p_attn, *p_P, *p_og, *p_gate, *p_gatg, *p_o, *p_dh,
          *p_node2, *p_nln, *p_h2;
    cudaGetSymbolAddress((void**)&p_bufA, g_bufA);
    cudaGetSymbolAddress((void**)&p_bufB, g_bufB);
    cudaGetSymbolAddress((void**)&p_h1,  g_h1);
    cudaGetSymbolAddress((void**)&p_node_msg, g_node_msg);
    cudaGetSymbolAddress((void**)&p_node_tgt, g_node_tgt);
    cudaGetSymbolAddress((void**)&p_ab,  g_ab);
    cudaGetSymbolAddress((void**)&p_attn,g_attn);
    cudaGetSymbolAddress((void**)&p_P,   g_P);
    cudaGetSymbolAddress((void**)&p_og,  g_og);
    cudaGetSymbolAddress((void**)&p_gate,g_gate);
    cudaGetSymbolAddress((void**)&p_gatg,g_gatg);
    cudaGetSymbolAddress((void**)&p_o,   g_o);
    cudaGetSymbolAddress((void**)&p_dh,  g_dh);
    cudaGetSymbolAddress((void**)&p_node2,g_node2);
    cudaGetSymbolAddress((void**)&p_nln, g_nln);
    cudaGetSymbolAddress((void**)&p_h2,  g_h2);

    float* out = (float*)d_out;

    // buffer aliases (lifetimes disjoint)
    float* p_msg0 = p_bufA;   // until ln_kernel reads it
    float* p_msg  = p_bufA;   // final messages (overwrites msg0 after it is dead)
    float* p_ln   = p_bufB;   // until h1 GEMM reads it
    float* p_t    = p_bufB;   // leaky(msg@W_msg) (overwrites ln after it is dead)

    // 1) node projections
    gemm<0>(node_repr, DIM, W_node_src, MSG, p_node_msg, MSG, ROWS_NODE, MSG, DIM);
    gemm<0>(node_repr, DIM, W_node_tgt, MSG, p_node_tgt, MSG, ROWS_NODE, MSG, DIM);

    // 2) msg0 = edge_repr@W_edge_msg + gather(node_msg)*mask_bw + node_tgt
    { EP e; e.a1 = p_node_msg; e.a2 = p_node_tgt; e.idx = edge_index; e.af = mask_bw;
      gemm<5>(edge_repr, MSG, W_edge_msg, MSG, p_msg0, MSG, ROWS_MSG, MSG, MSG, e); }

    // 3) msg MLP: LN -> gelu(W1) -> W2 (+mask-zero)
    ln_kernel<<<ROWS_MSG, 256>>>(p_msg0, p_ln, msg_ln_g, msg_ln_b, MSG);
    { EP e; e.bias = msg_b1;
      gemm<2>(p_ln, MSG, msg_W1, 4*MSG, p_h1, 4*MSG, ROWS_MSG, 4*MSG, MSG, e); }
    { EP e; e.bias = msg_b2; e.rm = edge_mask;
      gemm<4>(p_h1, 4*MSG, msg_W2, MSG, p_msg, MSG, ROWS_MSG, MSG, 4*MSG, e); }

    // 4) pooled gated path: gate_lin, pool, dh = o@W_out
    { EP e; e.bias = b_gate;
      gemm<1>(node_repr, DIM, W_gate, MSG, p_gate, MSG, ROWS_NODE, MSG, DIM, e); }
    pool_kernel<<<ROWS_NODE, 256>>>(p_msg, edge_mask, p_gate, p_o);
    gemm<0>(p_o, MSG, W_out, DIM, p_dh, DIM, ROWS_NODE, DIM, MSG);

    // 5) GAT path
    gemm<3>(p_msg, MSG, W_msg, MSG, p_t, MSG, ROWS_MSG, MSG, MSG);            // leaky(msg@W_msg)
    gemm<0>(p_t, MSG, W_attn_bias, NH, p_ab, NH, ROWS_MSG, NH, MSG);          // ab
    softmax_kernel<<<ROWS_NODE, 512>>>(p_ab, edge_mask, p_attn);
    pmat_kernel<<<ROWS_NODE, 256>>>(p_msg, p_attn, p_P);                      // P = attn^T msg
    { EP e; e.bias = b_gat_gate;
      gemm<1>(node_repr, DIM, W_gat_gate, NH*HD, p_gatg, NH*HD, ROWS_NODE, NH*HD, DIM, e); }
    for (int h = 0; h < NH; h++) {                                            // og = sigmoid(gatg)*(P@Wv) per head
        EP e; e.a1 = p_gatg + h * HD;
        gemm<8>(p_P + h * MSG, NH*MSG, W_gat_value + h * HD, NH*HD,
                p_og + h * HD, NH*HD, ROWS_NODE, HD, MSG, e);
    }

    // 6) node2 = node_repr + dh + og@W_gat_out
    { EP e; e.a1 = node_repr; e.a2 = p_dh;
      gemm<6>(p_og, NH*HD, W_gat_out, DIM, p_node2, DIM, ROWS_NODE, DIM, NH*HD, e); }

    // 7) node MLP + residual -> out
    ln_kernel<<<ROWS_NODE, 256>>>(p_node2, p_nln, node_ln_g, node_ln_b, DIM);
    { EP e; e.bias = node_b1;
      gemm<2>(p_nln, DIM, node_W1, 4*DIM, p_h2, 4*DIM, ROWS_NODE, 4*DIM, DIM, e); }
    { EP e; e.bias = node_b2; e.a1 = p_node2;
      gemm<7>(p_h2, 4*DIM, node_W2, DIM, out, DIM, ROWS_NODE, DIM, 4*DIM, e); }
}

// round 5
// speedup vs baseline: 1.6045x; 1.6045x over previous
#include <cuda_runtime.h>
#include <math.h>
#include <float.h>
#include <stdint.h>

// ---------------- problem constants ----------------
#define NB   2
#define NN   1024
#define NKE  32
#define DIM  512
#define MSG  256
#define NH   16
#define HD   64
#define ROWS_MSG  (NB*NN*NKE)   // 65536
#define ROWS_NODE (NB*NN)       // 2048

// ---------------- scratch (static device globals; no runtime alloc) ----------------
__device__ float g_bufA[ROWS_MSG*MSG];
__device__ float g_bufB[ROWS_MSG*MSG];
__device__ float g_h1  [ROWS_MSG*4*MSG];
__device__ float g_node_msg[ROWS_NODE*MSG];
__device__ float g_node_tgt[ROWS_NODE*MSG];
__device__ float g_ab  [ROWS_MSG*NH];
__device__ float g_attn[ROWS_MSG*NH];
__device__ float g_P   [ROWS_NODE*NH*MSG];
__device__ float g_og  [ROWS_NODE*NH*HD];
__device__ float g_gate[ROWS_NODE*MSG];
__device__ float g_gatg[ROWS_NODE*NH*HD];
__device__ float g_o   [ROWS_NODE*MSG];
__device__ float g_dh  [ROWS_NODE*DIM];
__device__ float g_node2[ROWS_NODE*DIM];
__device__ float g_nln [ROWS_NODE*DIM];
__device__ float g_h2  [ROWS_NODE*4*DIM];

// ---------------- tf32 tensor-core GEMM with fused epilogues ----------------
// Block tile 128x64, BK=16, 256 threads = 8 warps in 4(m) x 2(n), warp tile 32x32.
// mma.sync.aligned.m16n8k8.row.col.f32.tf32.tf32.f32
#define BM 128
#define BN 64
#define BK 16
#define APAD 4
#define BPAD 4

__device__ __forceinline__ float gelu_exact(float x) {
    return 0.5f * x * (1.0f + erff(x * 0.70710678118654752f));
}
__device__ __forceinline__ float sigmoidf_(float x) {
    return 1.0f / (1.0f + expf(-x));
}
__device__ __forceinline__ float f2tf32f(float x) {
    uint32_t r;
    asm("cvt.rna.tf32.f32 %0, %1;" : "=r"(r) : "f"(x));
    return __uint_as_float(r);
}
__device__ __forceinline__ void mma8(float* c, const uint32_t* a, const uint32_t* b) {
    asm("mma.sync.aligned.m16n8k8.row.col.f32.tf32.tf32.f32 "
        "{%0,%1,%2,%3},{%4,%5,%6,%7},{%8,%9},{%0,%1,%2,%3};"
        : "+f"(c[0]), "+f"(c[1]), "+f"(c[2]), "+f"(c[3])
        : "r"(a[0]), "r"(a[1]), "r"(a[2]), "r"(a[3]), "r"(b[0]), "r"(b[1]));
}

// MODE: 0 plain | 1 +bias | 2 gelu(+bias) | 3 leaky | 4 (+bias)*rowmask
//       5 msg0 (acc + gather(node_msg)*mask_bw + node_tgt)
//       6 aux1 + aux2 + acc | 7 aux1 + acc + bias | 8 sigmoid(aux1)*acc
// sA/sB/sC/sAux: per-blockIdx.z element offsets (batched per-head GEMMs)
template<int MODE>
__global__ __launch_bounds__(256) void gemm_tc(
    const float* __restrict__ A, int lda,
    const float* __restrict__ B, int ldb,
    float* __restrict__ C, int ldc,
    int M, int N, int K,
    const float* __restrict__ bias,
    const float* __restrict__ aux1,
    const float* __restrict__ aux2,
    const int*   __restrict__ idx,
    const float* __restrict__ auxf,
    const int*   __restrict__ rowmask,
    int sA, int sB, int sC, int sAux)
{
    A += (size_t)blockIdx.z * sA;
    B += (size_t)blockIdx.z * sB;
    C += (size_t)blockIdx.z * sC;
    const float* aux1z = aux1 ? aux1 + (size_t)blockIdx.z * sAux : aux1;

    __shared__ float As[BK][BM + APAD];   // K-major (transposed) A tile, tf32 bits
    __shared__ float Bs[BK][BN + BPAD];   // tf32 bits

    const int tid  = threadIdx.x;
    const int lane = tid & 31;
    const int warp = tid >> 5;
    const int warpM = warp >> 1;          // 0..3
    const int warpN = warp & 1;           // 0..1
    const int g  = lane >> 2;             // 0..7
    const int t4 = lane & 3;              // 0..3
    const int row0 = blockIdx.y * BM, col0 = blockIdx.x * BN;

    float acc[2][4][4];
    #pragma unroll
    for (int mi = 0; mi < 2; mi++)
        #pragma unroll
        for (int ni = 0; ni < 4; ni++)
            #pragma unroll
            for (int cr = 0; cr < 4; cr++) acc[mi][ni][cr] = 0.f;

    // A loader: thread -> (row = tid>>1, k-octet = (tid&1)*8), two float4
    const int a_m  = tid >> 1;
    const int a_k8 = (tid & 1) * 8;
    // B loader: thread -> (k row = tid>>4, 4 consecutive n)
    const int b_kk = tid >> 4;
    const int b_n4 = (tid & 15) * 4;

    for (int kt = 0; kt < K; kt += BK) {
        {
            int gr = row0 + a_m;
            float4 v0 = make_float4(0.f,0.f,0.f,0.f), v1 = v0;
            if (gr < M) {
                const float* ar = &A[(size_t)gr * lda + kt + a_k8];
                v0 = *reinterpret_cast<const float4*>(ar);
                v1 = *reinterpret_cast<const float4*>(ar + 4);
            }
            As[a_k8 + 0][a_m] = f2tf32f(v0.x);
            As[a_k8 + 1][a_m] = f2tf32f(v0.y);
            As[a_k8 + 2][a_m] = f2tf32f(v0.z);
            As[a_k8 + 3][a_m] = f2tf32f(v0.w);
            As[a_k8 + 4][a_m] = f2tf32f(v1.x);
            As[a_k8 + 5][a_m] = f2tf32f(v1.y);
            As[a_k8 + 6][a_m] = f2tf32f(v1.z);
            As[a_k8 + 7][a_m] = f2tf32f(v1.w);
        }
        {
            int gc = col0 + b_n4;
            const float* brow = &B[(size_t)(kt + b_kk) * ldb];
            if (gc + 3 < N) {
                float4 v = *reinterpret_cast<const float4*>(&brow[gc]);
                Bs[b_kk][b_n4 + 0] = f2tf32f(v.x);
                Bs[b_kk][b_n4 + 1] = f2tf32f(v.y);
                Bs[b_kk][b_n4 + 2] = f2tf32f(v.z);
                Bs[b_kk][b_n4 + 3] = f2tf32f(v.w);
            } else {
                #pragma unroll
                for (int j = 0; j < 4; j++)
                    Bs[b_kk][b_n4 + j] = (gc + j < N) ? f2tf32f(brow[gc + j]) : 0.f;
            }
        }
        __syncthreads();

        #pragma unroll
        for (int k8 = 0; k8 < BK; k8 += 8) {
            uint32_t af[2][4], bf[4][2];
            #pragma unroll
            for (int mi = 0; mi < 2; mi++) {
                int m0 = warpM * 32 + mi * 16 + g;
                af[mi][0] = __float_as_uint(As[k8 + t4    ][m0    ]);
                af[mi][1] = __float_as_uint(As[k8 + t4    ][m0 + 8]);
                af[mi][2] = __float_as_uint(As[k8 + t4 + 4][m0    ]);
                af[mi][3] = __float_as_uint(As[k8 + t4 + 4][m0 + 8]);
            }
            #pragma unroll
            for (int ni = 0; ni < 4; ni++) {
                int n0 = warpN * 32 + ni * 8 + g;
                bf[ni][0] = __float_as_uint(Bs[k8 + t4    ][n0]);
                bf[ni][1] = __float_as_uint(Bs[k8 + t4 + 4][n0]);
            }
            #pragma unroll
            for (int mi = 0; mi < 2; mi++)
                #pragma unroll
                for (int ni = 0; ni < 4; ni++)
                    mma8(acc[mi][ni], af[mi], bf[ni]);
        }
        __syncthreads();
    }

    // epilogue
    #pragma unroll
    for (int mi = 0; mi < 2; mi++) {
        #pragma unroll
        for (int cr = 0; cr < 4; cr++) {
            int r = row0 + warpM * 32 + mi * 16 + g + ((cr >> 1) ? 8 : 0);
            if (r >= M) continue;
            #pragma unroll
            for (int ni = 0; ni < 4; ni++) {
                int c = col0 + warpN * 32 + ni * 8 + t4 * 2 + (cr & 1);
                if (c >= N) continue;
                float v = acc[mi][ni][cr];
                if (MODE == 1) {
                    v += bias[c];
                } else if (MODE == 2) {
                    v = gelu_exact(v + bias[c]);
                } else if (MODE == 3) {
                    v = (v > 0.f) ? v : 0.01f * v;
                } else if (MODE == 4) {
                    v += bias[c];
                    if (rowmask[r] == 0) v = 0.f;
                } else if (MODE == 5) {
                    int bidx = r >> 15;            // 32768 msg rows per batch
                    int node = r >> 5;             // b*NN + n
                    v += aux1z[(size_t)(bidx*NN + idx[r]) * MSG + c] * auxf[r]
                       + aux2[(size_t)node * MSG + c];
                } else if (MODE == 6) {
                    v = aux1z[(size_t)r*ldc + c] + aux2[(size_t)r*ldc + c] + v;
                } else if (MODE == 7) {
                    v = aux1z[(size_t)r*ldc + c] + v + bias[c];
                } else if (MODE == 8) {
                    v *= sigmoidf_(aux1z[(size_t)r*ldc + c]);
                }
                C[(size_t)r * ldc + c] = v;
            }
        }
    }
}

// ---------------- LayerNorm (one block per row) ----------------
__global__ __launch_bounds__(256) void ln_kernel(
    const float* __restrict__ x, float* __restrict__ y,
    const float* __restrict__ g, const float* __restrict__ b, int width)
{
    int row = blockIdx.x;
    const float* xr = x + (size_t)row * width;
    float s = 0.f, sq = 0.f;
    for (int c = threadIdx.x; c < width; c += blockDim.x) {
        float v = xr[c]; s += v; sq += v * v;
    }
    __shared__ float sh[64];
    #pragma unroll
    for (int o = 16; o > 0; o >>= 1) {
        s  += __shfl_xor_sync(0xFFFFFFFFu, s,  o);
        sq += __shfl_xor_sync(0xFFFFFFFFu, sq, o);
    }
    int w = threadIdx.x >> 5, l = threadIdx.x & 31;
    if (l == 0) { sh[w] = s; sh[32 + w] = sq; }
    __syncthreads();
    if (threadIdx.x == 0) {
        float ts = 0.f, tq = 0.f;
        int nw = blockDim.x >> 5;
        for (int i = 0; i < nw; i++) { ts += sh[i]; tq += sh[32 + i]; }
        sh[0] = ts; sh[32] = tq;
    }
    __syncthreads();
    float mean = sh[0] / width;
    float var  = sh[32] / width - mean * mean;
    float rstd = rsqrtf(var + 1e-5f);
    float* yr = y + (size_t)row * width;
    for (int c = threadIdx.x; c < width; c += blockDim.x)
        yr[c] = (xr[c] - mean) * rstd * g[c] + b[c];
}

// ---------------- masked softmax over k, per (node, head) ----------------
__global__ __launch_bounds__(512) void softmax_kernel(
    const float* __restrict__ ab, const int* __restrict__ em,
    float* __restrict__ attn)
{
    int node = blockIdx.x;
    int h = threadIdx.x >> 5, k = threadIdx.x & 31;
    int ridx = node * NKE + k;
    float v = em[ridx] ? ab[(size_t)ridx * NH + h] : -FLT_MAX;
    float m = v;
    #pragma unroll
    for (int o = 16; o > 0; o >>= 1) m = fmaxf(m, __shfl_xor_sync(0xFFFFFFFFu, m, o));
    float e = expf(v - m);
    float s = e;
    #pragma unroll
    for (int o = 16; o > 0; o >>= 1) s += __shfl_xor_sync(0xFFFFFFFFu, s, o);
    attn[(size_t)ridx * NH + h] = e / s;
}

// ---------------- P[node,h,c] = sum_k attn[k,h] * msg[k,c] ----------------
__global__ __launch_bounds__(256) void pmat_kernel(
    const float* __restrict__ msg, const float* __restrict__ attn,
    float* __restrict__ P)
{
    __shared__ float ms[NKE][MSG];   // 32 KB
    __shared__ float as[NKE][NH];    // 2 KB
    int node = blockIdx.x;
    for (int e = threadIdx.x; e < NKE * MSG; e += 256)
        ms[e >> 8][e & 255] = msg[(size_t)node * NKE * MSG + e];
    for (int e = threadIdx.x; e < NKE * NH; e += 256)
        as[e >> 4][e & 15] = attn[(size_t)node * NKE * NH + e];
    __syncthreads();
    int c = threadIdx.x;   // 0..255
    #pragma unroll 1
    for (int h = 0; h < NH; h++) {
        float acc = 0.f;
        #pragma unroll
        for (int k = 0; k < NKE; k++) acc = fmaf(as[k][h], ms[k][c], acc);
        P[(size_t)node * NH * MSG + h * MSG + c] = acc;
    }
}

// ---------------- gated mean-pool over k ----------------
__global__ __launch_bounds__(256) void pool_kernel(
    const float* __restrict__ msg, const int* __restrict__ em,
    const float* __restrict__ gate_lin, float* __restrict__ o)
{
    int node = blockIdx.x;
    __shared__ float emf[NKE];
    __shared__ float cnt_s;
    if (threadIdx.x < NKE) emf[threadIdx.x] = (float)em[node * NKE + threadIdx.x];
    __syncthreads();
    if (threadIdx.x == 0) {
        float c = 0.f;
        for (int k = 0; k < NKE; k++) c += emf[k];
        cnt_s = c;
    }
    __syncthreads();
    float inv = 1.f / (cnt_s + 1e-6f);
    int c = threadIdx.x;   // 0..255
    float acc = 0.f;
    #pragma unroll
    for (int k = 0; k < NKE; k++)
        acc = fmaf(emf[k], msg[((size_t)node * NKE + k) * MSG + c], acc);
    float gl = gate_lin[(size_t)node * MSG + c];
    o[(size_t)node * MSG + c] = acc * inv * sigmoidf_(gl);
}

// ---------------- host side ----------------
struct EP {
    const float* bias = nullptr;
    const float* a1 = nullptr;
    const float* a2 = nullptr;
    const int*   idx = nullptr;
    const float* af = nullptr;
    const int*   rm = nullptr;
    int sA = 0, sB = 0, sC = 0, sAux = 0, Z = 1;
};

template<int MODE>
static void gemm(const float* A, int lda, const float* B, int ldb,
                 float* C, int ldc, int M, int N, int K, EP e = EP())
{
    dim3 g((N + BN - 1) / BN, (M + BM - 1) / BM, e.Z);
    gemm_tc<MODE><<<g, 256>>>(A, lda, B, ldb, C, ldc, M, N, K,
                              e.bias, e.a1, e.a2, e.idx, e.af, e.rm,
                              e.sA, e.sB, e.sC, e.sAux);
}

extern "C" void kernel_launch(void* const* d_in, const int* in_sizes, int n_in,
                              void* d_out, int out_size)
{
    const float* node_repr  = (const float*)d_in[0];
    const float* edge_repr  = (const float*)d_in[1];
    const int*   edge_index = (const int*)  d_in[2];
    const int*   edge_mask  = (const int*)  d_in[3];
    const float* mask_bw    = (const float*)d_in[4];
    const float* W_edge_msg = (const float*)d_in[5];
    const float* W_node_src = (const float*)d_in[6];
    const float* W_node_tgt = (const float*)d_in[7];
    const float* msg_ln_g   = (const float*)d_in[8];
    const float* msg_ln_b   = (const float*)d_in[9];
    const float* msg_W1     = (const float*)d_in[10];
    const float* msg_b1     = (const float*)d_in[11];
    const float* msg_W2     = (const float*)d_in[12];
    const float* msg_b2     = (const float*)d_in[13];
    const float* W_gate     = (const float*)d_in[14];
    const float* b_gate     = (const float*)d_in[15];
    const float* W_out      = (const float*)d_in[16];
    const float* W_msg      = (const float*)d_in[17];
    const float* W_attn_bias= (const float*)d_in[18];
    const float* W_gat_value= (const float*)d_in[19];
    const float* W_gat_gate = (const float*)d_in[20];
    const float* b_gat_gate = (const float*)d_in[21];
    const float* W_gat_out  = (const float*)d_in[22];
    const float* node_ln_g  = (const float*)d_in[23];
    const float* node_ln_b  = (const float*)d_in[24];
    const float* node_W1    = (const float*)d_in[25];
    const float* node_b1    = (const float*)d_in[26];
    const float* node_W2    = (const float*)d_in[27];
    const float* node_b2    = (const float*)d_in[28];

    float *p_bufA, *p_bufB, *p_h1, *p_node_msg, *p_node_tgt,
          *p_ab, *p_attn, *p_P, *p_og, *p_gate, *p_gatg, *p_o, *p_dh,
          *p_node2, *p_nln, *p_h2;
    cudaGetSymbolAddress((void**)&p_bufA, g_bufA);
    cudaGetSymbolAddress((void**)&p_bufB, g_bufB);
    cudaGetSymbolAddress((void**)&p_h1,  g_h1);
    cudaGetSymbolAddress((void**)&p_node_msg, g_node_msg);
    cudaGetSymbolAddress((void**)&p_node_tgt, g_node_tgt);
    cudaGetSymbolAddress((void**)&p_ab,  g_ab);
    cudaGetSymbolAddress((void**)&p_attn,g_attn);
    cudaGetSymbolAddress((void**)&p_P,   g_P);
    cudaGetSymbolAddress((void**)&p_og,  g_og);
    cudaGetSymbolAddress((void**)&p_gate,g_gate);
    cudaGetSymbolAddress((void**)&p_gatg,g_gatg);
    cudaGetSymbolAddress((void**)&p_o,   g_o);
    cudaGetSymbolAddress((void**)&p_dh,  g_dh);
    cudaGetSymbolAddress((void**)&p_node2,g_node2);
    cudaGetSymbolAddress((void**)&p_nln, g_nln);
    cudaGetSymbolAddress((void**)&p_h2,  g_h2);

    float* out = (float*)d_out;

    // buffer aliases (lifetimes disjoint)
    float* p_msg0 = p_bufA;   // until ln_kernel reads it
    float* p_msg  = p_bufA;   // final messages (overwrites msg0 after it is dead)
    float* p_ln   = p_bufB;   // until h1 GEMM reads it
    float* p_t    = p_bufB;   // leaky(msg@W_msg) (overwrites ln after it is dead)

    // 1) node projections
    gemm<0>(node_repr, DIM, W_node_src, MSG, p_node_msg, MSG, ROWS_NODE, MSG, DIM);
    gemm<0>(node_repr, DIM, W_node_tgt, MSG, p_node_tgt, MSG, ROWS_NODE, MSG, DIM);

    // 2) msg0 = edge_repr@W_edge_msg + gather(node_msg)*mask_bw + node_tgt
    { EP e; e.a1 = p_node_msg; e.a2 = p_node_tgt; e.idx = edge_index; e.af = mask_bw;
      gemm<5>(edge_repr, MSG, W_edge_msg, MSG, p_msg0, MSG, ROWS_MSG, MSG, MSG, e); }

    // 3) msg MLP: LN -> gelu(W1) -> W2 (+mask-zero)
    ln_kernel<<<ROWS_MSG, 256>>>(p_msg0, p_ln, msg_ln_g, msg_ln_b, MSG);
    { EP e; e.bias = msg_b1;
      gemm<2>(p_ln, MSG, msg_W1, 4*MSG, p_h1, 4*MSG, ROWS_MSG, 4*MSG, MSG, e); }
    { EP e; e.bias = msg_b2; e.rm = edge_mask;
      gemm<4>(p_h1, 4*MSG, msg_W2, MSG, p_msg, MSG, ROWS_MSG, MSG, 4*MSG, e); }

    // 4) pooled gated path: gate_lin, pool, dh = o@W_out
    { EP e; e.bias = b_gate;
      gemm<1>(node_repr, DIM, W_gate, MSG, p_gate, MSG, ROWS_NODE, MSG, DIM, e); }
    pool_kernel<<<ROWS_NODE, 256>>>(p_msg, edge_mask, p_gate, p_o);
    gemm<0>(p_o, MSG, W_out, DIM, p_dh, DIM, ROWS_NODE, DIM, MSG);

    // 5) GAT path
    gemm<3>(p_msg, MSG, W_msg, MSG, p_t, MSG, ROWS_MSG, MSG, MSG);            // leaky(msg@W_msg)
    gemm<0>(p_t, MSG, W_attn_bias, NH, p_ab, NH, ROWS_MSG, NH, MSG);          // ab
    softmax_kernel<<<ROWS_NODE, 512>>>(p_ab, edge_mask, p_attn);
    pmat_kernel<<<ROWS_NODE, 256>>>(p_msg, p_attn, p_P);                      // P = attn^T msg
    { EP e; e.bias = b_gat_gate;
      gemm<1>(node_repr, DIM, W_gat_gate, NH*HD, p_gatg, NH*HD, ROWS_NODE, NH*HD, DIM, e); }
    { EP e; e.a1 = p_gatg;                                                    // batched per-head, grid.z=NH
      e.Z = NH; e.sA = MSG; e.sB = HD; e.sC = HD; e.sAux = HD;
      gemm<8>(p_P, NH*MSG, W_gat_value, NH*HD,
              p_og, NH*HD, ROWS_NODE, HD, MSG, e); }

    // 6) node2 = node_repr + dh + og@W_gat_out
    { EP e; e.a1 = node_repr; e.a2 = p_dh;
      gemm<6>(p_og, NH*HD, W_gat_out, DIM, p_node2, DIM, ROWS_NODE, DIM, NH*HD, e); }

    // 7) node MLP + residual -> out
    ln_kernel<<<ROWS_NODE, 256>>>(p_node2, p_nln, node_ln_g, node_ln_b, DIM);
    { EP e; e.bias = node_b1;
      gemm<2>(p_nln, DIM, node_W1, 4*DIM, p_h2, 4*DIM, ROWS_NODE, 4*DIM, DIM, e); }
    { EP e; e.bias = node_b2; e.a1 = p_node2;
      gemm<7>(p_h2, 4*DIM, node_W2, DIM, out, DIM, ROWS_NODE, DIM, 4*DIM, e); }
}

// round 8
// speedup vs baseline: 2.9566x; 1.8427x over previous
#include <cuda_runtime.h>
#include <math.h>
#include <float.h>
#include <stdint.h>

// ---------------- problem constants ----------------
#define NB   2
#define NN   1024
#define NKE  32
#define DIM  512
#define MSG  256
#define NH   16
#define HD   64
#define ROWS_MSG  (NB*NN*NKE)   // 65536
#define ROWS_NODE (NB*NN)       // 2048

// ---------------- scratch (static device globals; no runtime alloc) ----------------
__device__ float g_bufA[ROWS_MSG*MSG];
__device__ float g_bufB[ROWS_MSG*MSG];
__device__ float g_h1  [ROWS_MSG*4*MSG];
__device__ float g_node_msg[ROWS_NODE*MSG];
__device__ float g_node_tgt[ROWS_NODE*MSG];
__device__ float g_ab  [ROWS_MSG*NH];
__device__ float g_attn[ROWS_MSG*NH];
__device__ float g_P   [ROWS_NODE*NH*MSG];
__device__ float g_og  [ROWS_NODE*NH*HD];
__device__ float g_gate[ROWS_NODE*MSG];
__device__ float g_gatg[ROWS_NODE*NH*HD];
__device__ float g_o   [ROWS_NODE*MSG];
__device__ float g_dh  [ROWS_NODE*DIM];
__device__ float g_node2[ROWS_NODE*DIM];
__device__ float g_nln [ROWS_NODE*DIM];
__device__ float g_h2  [ROWS_NODE*4*DIM];

// ---------------- tf32 tensor-core GEMM, cp.async 2-stage pipeline ----------------
// Block tile 128x64, BK=16, 128 threads = 4 warps in 2(m) x 2(n), warp tile 64x32.
// A smem: [BM][AS_STR] row-major (k contiguous) ; B smem: [BK][BS_STR] (n contiguous).
// tf32 conversion skipped: HMMA truncates low mantissa bits.
#define BM 128
#define BN 64
#define BK 16
#define AS_STR 20
#define BS_STR 72
#define A_TILE_F (BM*AS_STR)   // 2560 floats
#define B_TILE_F (BK*BS_STR)   // 1152 floats

__device__ __forceinline__ float gelu_exact(float x) {
    return 0.5f * x * (1.0f + erff(x * 0.70710678118654752f));
}
__device__ __forceinline__ float sigmoidf_(float x) {
    return 1.0f / (1.0f + expf(-x));
}
__device__ __forceinline__ void mma8(float* c, const uint32_t* a, const uint32_t* b) {
    asm("mma.sync.aligned.m16n8k8.row.col.f32.tf32.tf32.f32 "
        "{%0,%1,%2,%3},{%4,%5,%6,%7},{%8,%9},{%0,%1,%2,%3};"
        : "+f"(c[0]), "+f"(c[1]), "+f"(c[2]), "+f"(c[3])
        : "r"(a[0]), "r"(a[1]), "r"(a[2]), "r"(a[3]), "r"(b[0]), "r"(b[1]));
}
__device__ __forceinline__ void cp16(uint32_t dst, const void* src, int bytes) {
    asm volatile("cp.async.ca.shared.global [%0], [%1], 16, %2;\n"
                 :: "r"(dst), "l"(src), "r"(bytes));
}

// MODE: 0 plain | 1 +bias | 2 gelu(+bias) | 3 leaky | 4 (+bias)*rowmask
//       5 msg0 (acc + gather(node_msg)*mask_bw + node_tgt)
//       6 aux1 + aux2 + acc | 7 aux1 + acc + bias | 8 sigmoid(aux1)*acc
// Requires: M % 128 == 0, K % 16 == 0 (true for every call site).
template<int MODE>
__global__ __launch_bounds__(128) void gemm_tc(
    const float* __restrict__ A, int lda,
    const float* __restrict__ B, int ldb,
    float* __restrict__ C, int ldc,
    int M, int N, int K,
    const float* __restrict__ bias,
    const float* __restrict__ aux1,
    const float* __restrict__ aux2,
    const int*   __restrict__ idx,
    const float* __restrict__ auxf,
    const int*   __restrict__ rowmask,
    int sA, int sB, int sC, int sAux)
{
    A += (size_t)blockIdx.z * sA;
    B += (size_t)blockIdx.z * sB;
    C += (size_t)blockIdx.z * sC;
    const float* aux1z = aux1 ? aux1 + (size_t)blockIdx.z * sAux : aux1;

    __shared__ __align__(16) float sm[2*A_TILE_F + 2*B_TILE_F];
    uint32_t smem_u32 = (uint32_t)__cvta_generic_to_shared(sm);

    const int tid  = threadIdx.x;
    const int lane = tid & 31;
    const int warp = tid >> 5;
    const int warpM = warp >> 1;          // 0..1
    const int warpN = warp & 1;           // 0..1
    const int g  = lane >> 2;             // 0..7
    const int t4 = lane & 3;              // 0..3
    const int row0 = blockIdx.y * BM, col0 = blockIdx.x * BN;

    float ac[4][4][4];
    #pragma unroll
    for (int mi = 0; mi < 4; mi++)
        #pragma unroll
        for (int ni = 0; ni < 4; ni++)
            #pragma unroll
            for (int cr = 0; cr < 4; cr++) ac[mi][ni][cr] = 0.f;

    const int T = K / BK;

    // ---- stage loader ----
    auto load_stage = [&](int kt, int s) {
        // A tile: 128 rows x 16 k = 512 16B-chunks; 4 per thread
        #pragma unroll
        for (int i = 0; i < 4; i++) {
            int c = i * 128 + tid;
            int row = c >> 2, k4 = (c & 3) << 2;
            const float* src = A + (size_t)(row0 + row) * lda + kt + k4;
            uint32_t dst = smem_u32 + ((s * A_TILE_F + row * AS_STR + k4) << 2);
            cp16(dst, src, 16);
        }
        // B tile: 16 k-rows x 64 n = 256 chunks; 2 per thread
        #pragma unroll
        for (int i = 0; i < 2; i++) {
            int c = i * 128 + tid;
            int kk = c >> 4, n4 = (c & 15) << 2;
            int gc = col0 + n4;
            int rem = N - gc;
            int bytes = rem >= 4 ? 16 : (rem > 0 ? rem * 4 : 0);
            const float* src = B + (size_t)(kt + kk) * ldb + (rem > 0 ? gc : 0);
            uint32_t dst = smem_u32 + ((2 * A_TILE_F + s * B_TILE_F + kk * BS_STR + n4) << 2);
            cp16(dst, src, bytes);
        }
        asm volatile("cp.async.commit_group;\n");
    };

    load_stage(0, 0);

    for (int t = 0; t < T; t++) {
        int s = t & 1;
        if (t + 1 < T) {
            load_stage((t + 1) * BK, s ^ 1);
            asm volatile("cp.async.wait_group 1;\n");
        } else {
            asm volatile("cp.async.wait_group 0;\n");
        }
        __syncthreads();

        const float* As_ = &sm[s * A_TILE_F];
        const float* Bs_ = &sm[2 * A_TILE_F + s * B_TILE_F];

        #pragma unroll
        for (int k8 = 0; k8 < BK; k8 += 8) {
            uint32_t af[4][4], bf[4][2];
            #pragma unroll
            for (int mi = 0; mi < 4; mi++) {
                int m0 = warpM * 64 + mi * 16 + g;
                af[mi][0] = __float_as_uint(As_[(m0    ) * AS_STR + k8 + t4    ]);
                af[mi][1] = __float_as_uint(As_[(m0 + 8) * AS_STR + k8 + t4    ]);
                af[mi][2] = __float_as_uint(As_[(m0    ) * AS_STR + k8 + t4 + 4]);
                af[mi][3] = __float_as_uint(As_[(m0 + 8) * AS_STR + k8 + t4 + 4]);
            }
            #pragma unroll
            for (int ni = 0; ni < 4; ni++) {
                int n0 = warpN * 32 + ni * 8 + g;
                bf[ni][0] = __float_as_uint(Bs_[(k8 + t4    ) * BS_STR + n0]);
                bf[ni][1] = __float_as_uint(Bs_[(k8 + t4 + 4) * BS_STR + n0]);
            }
            #pragma unroll
            for (int mi = 0; mi < 4; mi++)
                #pragma unroll
                for (int ni = 0; ni < 4; ni++)
                    mma8(ac[mi][ni], af[mi], bf[ni]);
        }
        __syncthreads();
    }

    // epilogue
    #pragma unroll
    for (int mi = 0; mi < 4; mi++) {
        #pragma unroll
        for (int cr = 0; cr < 4; cr++) {
            int r = row0 + warpM * 64 + mi * 16 + g + ((cr >> 1) ? 8 : 0);
            #pragma unroll
            for (int ni = 0; ni < 4; ni++) {
                int c = col0 + warpN * 32 + ni * 8 + t4 * 2 + (cr & 1);
                if (c >= N) continue;
                float v = ac[mi][ni][cr];
                if (MODE == 1) {
                    v += bias[c];
                } else if (MODE == 2) {
                    v = gelu_exact(v + bias[c]);
                } else if (MODE == 3) {
                    v = (v > 0.f) ? v : 0.01f * v;
                } else if (MODE == 4) {
                    v += bias[c];
                    if (rowmask[r] == 0) v = 0.f;
                } else if (MODE == 5) {
                    int bidx = r >> 15;            // 32768 msg rows per batch
                    int node = r >> 5;             // b*NN + n
                    v += aux1z[(size_t)(bidx*NN + idx[r]) * MSG + c] * auxf[r]
                       + aux2[(size_t)node * MSG + c];
                } else if (MODE == 6) {
                    v = aux1z[(size_t)r*ldc + c] + aux2[(size_t)r*ldc + c] + v;
                } else if (MODE == 7) {
                    v = aux1z[(size_t)r*ldc + c] + v + bias[c];
                } else if (MODE == 8) {
                    v *= sigmoidf_(aux1z[(size_t)r*ldc + c]);
                }
                C[(size_t)r * ldc + c] = v;
            }
        }
    }
}

// ---------------- LayerNorm: one warp per row, float4 ----------------
// width must be a multiple of 128 (256 and 512 here). grid = rows/8, block 256.
__global__ __launch_bounds__(256) void ln_warp_kernel(
    const float* __restrict__ x, float* __restrict__ y,
    const float* __restrict__ g, const float* __restrict__ b, int width)
{
    int wid  = threadIdx.x >> 5;
    int lane = threadIdx.x & 31;
    int row  = blockIdx.x * 8 + wid;
    const float4* xr = reinterpret_cast<const float4*>(x + (size_t)row * width);
    int w4 = width >> 2;

    float s = 0.f, sq = 0.f;
    for (int i = lane; i < w4; i += 32) {
        float4 v = xr[i];
        s  += v.x + v.y + v.z + v.w;
        sq += v.x*v.x + v.y*v.y + v.z*v.z + v.w*v.w;
    }
    #pragma unroll
    for (int o = 16; o > 0; o >>= 1) {
        s  += __shfl_xor_sync(0xFFFFFFFFu, s,  o);
        sq += __shfl_xor_sync(0xFFFFFFFFu, sq, o);
    }
    float mean = s / width;
    float var  = sq / width - mean * mean;
    float rstd = rsqrtf(var + 1e-5f);

    const float4* g4 = reinterpret_cast<const float4*>(g);
    const float4* b4 = reinterpret_cast<const float4*>(b);
    float4* yr = reinterpret_cast<float4*>(y + (size_t)row * width);
    for (int i = lane; i < w4; i += 32) {
        float4 v = xr[i], gg = g4[i], bb = b4[i];
        float4 o;
        o.x = (v.x - mean) * rstd * gg.x + bb.x;
        o.y = (v.y - mean) * rstd * gg.y + bb.y;
        o.z = (v.z - mean) * rstd * gg.z + bb.z;
        o.w = (v.w - mean) * rstd * gg.w + bb.w;
        yr[i] = o;
    }
}

// ---------------- masked softmax over k, per (node, head) ----------------
__global__ __launch_bounds__(512) void softmax_kernel(
    const float* __restrict__ ab, const int* __restrict__ em,
    float* __restrict__ attn)
{
    int node = blockIdx.x;
    int h = threadIdx.x >> 5, k = threadIdx.x & 31;
    int ridx = node * NKE + k;
    float v = em[ridx] ? ab[(size_t)ridx * NH + h] : -FLT_MAX;
    float m = v;
    #pragma unroll
    for (int o = 16; o > 0; o >>= 1) m = fmaxf(m, __shfl_xor_sync(0xFFFFFFFFu, m, o));
    float e = expf(v - m);
    float s = e;
    #pragma unroll
    for (int o = 16; o > 0; o >>= 1) s += __shfl_xor_sync(0xFFFFFFFFu, s, o);
    attn[(size_t)ridx * NH + h] = e / s;
}

// ---------------- P[node,h,c] = sum_k attn[k,h] * msg[k,c] ----------------
__global__ __launch_bounds__(256) void pmat_kernel(
    const float* __restrict__ msg, const float* __restrict__ attn,
    float* __restrict__ P)
{
    __shared__ float ms[NKE][MSG];   // 32 KB
    __shared__ float as[NKE][NH];    // 2 KB
    int node = blockIdx.x;
    for (int e = threadIdx.x; e < NKE * MSG; e += 256)
        ms[e >> 8][e & 255] = msg[(size_t)node * NKE * MSG + e];
    for (int e = threadIdx.x; e < NKE * NH; e += 256)
        as[e >> 4][e & 15] = attn[(size_t)node * NKE * NH + e];
    __syncthreads();
    int c = threadIdx.x;   // 0..255
    #pragma unroll 1
    for (int h = 0; h < NH; h++) {
        float acc = 0.f;
        #pragma unroll
        for (int k = 0; k < NKE; k++) acc = fmaf(as[k][h], ms[k][c], acc);
        P[(size_t)node * NH * MSG + h * MSG + c] = acc;
    }
}

// ---------------- gated mean-pool over k ----------------
__global__ __launch_bounds__(256) void pool_kernel(
    const float* __restrict__ msg, const int* __restrict__ em,
    const float* __restrict__ gate_lin, float* __restrict__ o)
{
    int node = blockIdx.x;
    __shared__ float emf[NKE];
    __shared__ float cnt_s;
    if (threadIdx.x < NKE) emf[threadIdx.x] = (float)em[node * NKE + threadIdx.x];
    __syncthreads();
    if (threadIdx.x == 0) {
        float c = 0.f;
        for (int k = 0; k < NKE; k++) c += emf[k];
        cnt_s = c;
    }
    __syncthreads();
    float inv = 1.f / (cnt_s + 1e-6f);
    int c = threadIdx.x;   // 0..255
    float acc = 0.f;
    #pragma unroll
    for (int k = 0; k < NKE; k++)
        acc = fmaf(emf[k], msg[((size_t)node * NKE + k) * MSG + c], acc);
    float gl = gate_lin[(size_t)node * MSG + c];
    o[(size_t)node * MSG + c] = acc * inv * sigmoidf_(gl);
}

// ---------------- host side ----------------
struct EP {
    const float* bias = nullptr;
    const float* a1 = nullptr;
    const float* a2 = nullptr;
    const int*   idx = nullptr;
    const float* af = nullptr;
    const int*   rm = nullptr;
    int sA = 0, sB = 0, sC = 0, sAux = 0, Z = 1;
};

template<int MODE>
static void gemm(const float* A, int lda, const float* B, int ldb,
                 float* C, int ldc, int M, int N, int K, EP e = EP())
{
    dim3 g((N + BN - 1) / BN, (M + BM - 1) / BM, e.Z);
    gemm_tc<MODE><<<g, 128>>>(A, lda, B, ldb, C, ldc, M, N, K,
                              e.bias, e.a1, e.a2, e.idx, e.af, e.rm,
                              e.sA, e.sB, e.sC, e.sAux);
}

extern "C" void kernel_launch(void* const* d_in, const int* in_sizes, int n_in,
                              void* d_out, int out_size)
{
    const float* node_repr  = (const float*)d_in[0];
    const float* edge_repr  = (const float*)d_in[1];
    const int*   edge_index = (const int*)  d_in[2];
    const int*   edge_mask  = (const int*)  d_in[3];
    const float* mask_bw    = (const float*)d_in[4];
    const float* W_edge_msg = (const float*)d_in[5];
    const float* W_node_src = (const float*)d_in[6];
    const float* W_node_tgt = (const float*)d_in[7];
    const float* msg_ln_g   = (const float*)d_in[8];
    const float* msg_ln_b   = (const float*)d_in[9];
    const float* msg_W1     = (const float*)d_in[10];
    const float* msg_b1     = (const float*)d_in[11];
    const float* msg_W2     = (const float*)d_in[12];
    const float* msg_b2     = (const float*)d_in[13];
    const float* W_gate     = (const float*)d_in[14];
    const float* b_gate     = (const float*)d_in[15];
    const float* W_out      = (const float*)d_in[16];
    const float* W_msg      = (const float*)d_in[17];
    const float* W_attn_bias= (const float*)d_in[18];
    const float* W_gat_value= (const float*)d_in[19];
    const float* W_gat_gate = (const float*)d_in[20];
    const float* b_gat_gate = (const float*)d_in[21];
    const float* W_gat_out  = (const float*)d_in[22];
    const float* node_ln_g  = (const float*)d_in[23];
    const float* node_ln_b  = (const float*)d_in[24];
    const float* node_W1    = (const float*)d_in[25];
    const float* node_b1    = (const float*)d_in[26];
    const float* node_W2    = (const float*)d_in[27];
    const float* node_b2    = (const float*)d_in[28];

    float *p_bufA, *p_bufB, *p_h1, *p_node_msg, *p_node_tgt,
          *p_ab, *p_attn, *p_P, *p_og, *p_gate, *p_gatg, *p_o, *p_dh,
          *p_node2, *p_nln, *p_h2;
    cudaGetSymbolAddress((void**)&p_bufA, g_bufA);
    cudaGetSymbolAddress((void**)&p_bufB, g_bufB);
    cudaGetSymbolAddress((void**)&p_h1,  g_h1);
    cudaGetSymbolAddress((void**)&p_node_msg, g_node_msg);
    cudaGetSymbolAddress((void**)&p_node_tgt, g_node_tgt);
    cudaGetSymbolAddress((void**)&p_ab,  g_ab);
    cudaGetSymbolAddress((void**)&p_attn,g_attn);
    cudaGetSymbolAddress((void**)&p_P,   g_P);
    cudaGetSymbolAddress((void**)&p_og,  g_og);
    cudaGetSymbolAddress((void**)&p_gate,g_gate);
    cudaGetSymbolAddress((void**)&p_gatg,g_gatg);
    cudaGetSymbolAddress((void**)&p_o,   g_o);
    cudaGetSymbolAddress((void**)&p_dh,  g_dh);
    cudaGetSymbolAddress((void**)&p_node2,g_node2);
    cudaGetSymbolAddress((void**)&p_nln, g_nln);
    cudaGetSymbolAddress((void**)&p_h2,  g_h2);

    float* out = (float*)d_out;

    // buffer aliases (lifetimes disjoint)
    float* p_msg0 = p_bufA;   // until ln reads it
    float* p_msg  = p_bufA;   // final messages (overwrites msg0 after it is dead)
    float* p_ln   = p_bufB;   // until h1 GEMM reads it
    float* p_t    = p_bufB;   // leaky(msg@W_msg) (overwrites ln after it is dead)

    // 1) node projections
    gemm<0>(node_repr, DIM, W_node_src, MSG, p_node_msg, MSG, ROWS_NODE, MSG, DIM);
    gemm<0>(node_repr, DIM, W_node_tgt, MSG, p_node_tgt, MSG, ROWS_NODE, MSG, DIM);

    // 2) msg0 = edge_repr@W_edge_msg + gather(node_msg)*mask_bw + node_tgt
    { EP e; e.a1 = p_node_msg; e.a2 = p_node_tgt; e.idx = edge_index; e.af = mask_bw;
      gemm<5>(edge_repr, MSG, W_edge_msg, MSG, p_msg0, MSG, ROWS_MSG, MSG, MSG, e); }

    // 3) msg MLP: LN -> gelu(W1) -> W2 (+mask-zero)
    ln_warp_kernel<<<ROWS_MSG/8, 256>>>(p_msg0, p_ln, msg_ln_g, msg_ln_b, MSG);
    { EP e; e.bias = msg_b1;
      gemm<2>(p_ln, MSG, msg_W1, 4*MSG, p_h1, 4*MSG, ROWS_MSG, 4*MSG, MSG, e); }
    { EP e; e.bias = msg_b2; e.rm = edge_mask;
      gemm<4>(p_h1, 4*MSG, msg_W2, MSG, p_msg, MSG, ROWS_MSG, MSG, 4*MSG, e); }

    // 4) pooled gated path: gate_lin, pool, dh = o@W_out
    { EP e; e.bias = b_gate;
      gemm<1>(node_repr, DIM, W_gate, MSG, p_gate, MSG, ROWS_NODE, MSG, DIM, e); }
    pool_kernel<<<ROWS_NODE, 256>>>(p_msg, edge_mask, p_gate, p_o);
    gemm<0>(p_o, MSG, W_out, DIM, p_dh, DIM, ROWS_NODE, DIM, MSG);

    // 5) GAT path
    gemm<3>(p_msg, MSG, W_msg, MSG, p_t, MSG, ROWS_MSG, MSG, MSG);            // leaky(msg@W_msg)
    gemm<0>(p_t, MSG, W_attn_bias, NH, p_ab, NH, ROWS_MSG, NH, MSG);          // ab
    softmax_kernel<<<ROWS_NODE, 512>>>(p_ab, edge_mask, p_attn);
    pmat_kernel<<<ROWS_NODE, 256>>>(p_msg, p_attn, p_P);                      // P = attn^T msg
    { EP e; e.bias = b_gat_gate;
      gemm<1>(node_repr, DIM, W_gat_gate, NH*HD, p_gatg, NH*HD, ROWS_NODE, NH*HD, DIM, e); }
    { EP e; e.a1 = p_gatg;                                                    // batched per-head, grid.z=NH
      e.Z = NH; e.sA = MSG; e.sB = HD; e.sC = HD; e.sAux = HD;
      gemm<8>(p_P, NH*MSG, W_gat_value, NH*HD,
              p_og, NH*HD, ROWS_NODE, HD, MSG, e); }

    // 6) node2 = node_repr + dh + og@W_gat_out
    { EP e; e.a1 = node_repr; e.a2 = p_dh;
      gemm<6>(p_og, NH*HD, W_gat_out, DIM, p_node2, DIM, ROWS_NODE, DIM, NH*HD, e); }

    // 7) node MLP + residual -> out
    ln_warp_kernel<<<ROWS_NODE/8, 256>>>(p_node2, p_nln, node_ln_g, node_ln_b, DIM);
    { EP e; e.bias = node_b1;
      gemm<2>(p_nln, DIM, node_W1, 4*DIM, p_h2, 4*DIM, ROWS_NODE, 4*DIM, DIM, e); }
    { EP e; e.bias = node_b2; e.a1 = p_node2;
      gemm<7>(p_h2, 4*DIM, node_W2, DIM, out, DIM, ROWS_NODE, DIM, 4*DIM, e); }
}